// round 1
// baseline (speedup 1.0000x reference)
#include <cuda_runtime.h>

// SuperpositionNeuron: out[r] = should_measure ? interfered[argmax(interfered+gumbel)]
//                                              : mean(interfered)
// interfered = sigmoid(x@W + b) @ M^T
// B = 1048576 rows, D = 128, S = 4. Pure HBM-streaming kernel.

#define D_DIM 128
#define S_DIM 4

__global__ void __launch_bounds__(256) sn_kernel(
    const float* __restrict__ x,       // [B, 128]
    const float* __restrict__ W,       // [128, 4]
    const float* __restrict__ b,       // [4]
    const float* __restrict__ M,       // [4, 4]
    const float* __restrict__ thrp,    // [1]
    const float* __restrict__ noise,   // [B, 1]
    const float* __restrict__ u,       // [B, 1]
    const float* __restrict__ gumbel,  // [B, 4]
    float* __restrict__ out,           // [B, 1]
    int B)
{
    const int lane = threadIdx.x & 31;
    const int q    = lane & 7;   // position within row (8 lanes per row)
    const int sub  = lane >> 3;  // which of the 4 rows this warp owns

    // global warp id -> base row
    const int warp_id = blockIdx.x * (blockDim.x >> 5) + (threadIdx.x >> 5);
    const int row = warp_id * 4 + sub;
    if (row >= B) return;

    // ---- preload W rows this lane will ever touch: e = k*32 + q*4 + j ----
    // Wr[k][j] = W[e][0..3]  (W is [128,4] row-major -> row e is a float4)
    float4 Wr[4][4];
#pragma unroll
    for (int k = 0; k < 4; k++) {
#pragma unroll
        for (int j = 0; j < 4; j++) {
            Wr[k][j] = __ldg((const float4*)(W + 4 * (k * 32 + q * 4 + j)));
        }
    }

    // ---- hoisted small constants (register-resident, same for all rows) ----
    const float  thr = __ldg(thrp);
    const float4 bv  = __ldg((const float4*)b);
    const float4 M0  = __ldg((const float4*)(M + 0));
    const float4 M1  = __ldg((const float4*)(M + 4));
    const float4 M2  = __ldg((const float4*)(M + 8));
    const float4 M3  = __ldg((const float4*)(M + 12));

    // ---- dot products: acc[s] = sum_d x[row][d] * W[d][s] ----
    const float4* xr = (const float4*)(x + (long)row * D_DIM);
    float acc0 = 0.f, acc1 = 0.f, acc2 = 0.f, acc3 = 0.f;
#pragma unroll
    for (int k = 0; k < 4; k++) {
        float4 xv = xr[k * 8 + q];  // elements k*32 + q*4 .. +3 of this row
        acc0 += xv.x * Wr[k][0].x + xv.y * Wr[k][1].x + xv.z * Wr[k][2].x + xv.w * Wr[k][3].x;
        acc1 += xv.x * Wr[k][0].y + xv.y * Wr[k][1].y + xv.z * Wr[k][2].y + xv.w * Wr[k][3].y;
        acc2 += xv.x * Wr[k][0].z + xv.y * Wr[k][1].z + xv.z * Wr[k][2].z + xv.w * Wr[k][3].z;
        acc3 += xv.x * Wr[k][0].w + xv.y * Wr[k][1].w + xv.z * Wr[k][2].w + xv.w * Wr[k][3].w;
    }

    // ---- reduce across the 8 lanes of this row (xor stays inside the group) ----
#pragma unroll
    for (int off = 4; off > 0; off >>= 1) {
        acc0 += __shfl_xor_sync(0xffffffffu, acc0, off);
        acc1 += __shfl_xor_sync(0xffffffffu, acc1, off);
        acc2 += __shfl_xor_sync(0xffffffffu, acc2, off);
        acc3 += __shfl_xor_sync(0xffffffffu, acc3, off);
    }

    if (q == 0) {
        // state = sigmoid(acc + b)
        float s0 = 1.f / (1.f + __expf(-(acc0 + bv.x)));
        float s1 = 1.f / (1.f + __expf(-(acc1 + bv.y)));
        float s2 = 1.f / (1.f + __expf(-(acc2 + bv.z)));
        float s3 = 1.f / (1.f + __expf(-(acc3 + bv.w)));

        // interfered[i] = sum_j M[i][j] * state[j]
        float i0 = M0.x * s0 + M0.y * s1 + M0.z * s2 + M0.w * s3;
        float i1 = M1.x * s0 + M1.y * s1 + M1.z * s2 + M1.w * s3;
        float i2 = M2.x * s0 + M2.y * s1 + M2.z * s2 + M2.w * s3;
        float i3 = M3.x * s0 + M3.y * s1 + M3.z * s2 + M3.w * s3;

        // bernoulli collapse decision
        float nz = __ldg(noise + row);
        float mp = 1.f / (1.f + __expf(-(nz + thr)));
        bool should_measure = __ldg(u + row) < mp;

        // gumbel-argmax (first-max tiebreak, matching jnp.argmax)
        float4 g = __ldg((const float4*)(gumbel + (long)row * 4));
        float v0 = i0 + g.x, v1 = i1 + g.y, v2 = i2 + g.z, v3 = i3 + g.w;
        float best = v0, mv = i0;
        if (v1 > best) { best = v1; mv = i1; }
        if (v2 > best) { best = v2; mv = i2; }
        if (v3 > best) { best = v3; mv = i3; }

        float mean = 0.25f * (i0 + i1 + i2 + i3);
        out[row] = should_measure ? mv : mean;
    }
}

extern "C" void kernel_launch(void* const* d_in, const int* in_sizes, int n_in,
                              void* d_out, int out_size)
{
    const float* x      = (const float*)d_in[0];
    const float* W      = (const float*)d_in[1];
    const float* b      = (const float*)d_in[2];
    const float* M      = (const float*)d_in[3];
    const float* thr    = (const float*)d_in[4];
    const float* noise  = (const float*)d_in[5];
    const float* u      = (const float*)d_in[6];
    const float* gumbel = (const float*)d_in[7];
    float* out = (float*)d_out;

    int B = in_sizes[0] / D_DIM;          // 1048576
    int rows_per_block = 32;              // 8 warps * 4 rows
    int blocks = (B + rows_per_block - 1) / rows_per_block;
    sn_kernel<<<blocks, 256>>>(x, W, b, M, thr, noise, u, gumbel, out, B);
}

// round 2
// speedup vs baseline: 1.3354x; 1.3354x over previous
#include <cuda_runtime.h>

// SuperpositionNeuron: out[r] = should_measure ? interfered[argmax(interfered+gumbel)]
//                                              : mean(interfered)
// interfered = sigmoid(x@W + b) @ M^T ;  B = 1048576, D = 128, S = 4.
//
// R2: persistent grid-stride warps. W/b/M/thr loaded into registers ONCE per
// thread and reused across 16 row-groups (kills the 64-wavefront/group W
// reload that made R1 L1-bound at 97%). Reduced 8-lane x 4-value reduction
// from 12 shuffles to 7 via pair-splitting.

#define D_DIM 128

__global__ void __launch_bounds__(256, 2) sn_kernel(
    const float* __restrict__ x,       // [B, 128]
    const float* __restrict__ W,       // [128, 4]
    const float* __restrict__ b,       // [4]
    const float* __restrict__ M,       // [4, 4]
    const float* __restrict__ thrp,    // [1]
    const float* __restrict__ noise,   // [B]
    const float* __restrict__ u,       // [B]
    const float* __restrict__ gumbel,  // [B, 4]
    float* __restrict__ out,           // [B]
    int B, int rows_per_iter)
{
    const int lane = threadIdx.x & 31;
    const int q    = lane & 7;   // position within row (8 lanes per row)
    const int sub  = lane >> 3;  // which of the 4 rows this warp owns

    const int warp_id = blockIdx.x * (blockDim.x >> 5) + (threadIdx.x >> 5);

    // ---- load-once constants (live in registers across the whole loop) ----
    float4 Wr[4][4];                    // W rows k*32 + q*4 + j
#pragma unroll
    for (int k = 0; k < 4; k++)
#pragma unroll
        for (int j = 0; j < 4; j++)
            Wr[k][j] = __ldg((const float4*)(W + 4 * (k * 32 + q * 4 + j)));

    const float  thr = __ldg(thrp);
    const float4 bv  = __ldg((const float4*)b);
    const float4 M0  = __ldg((const float4*)(M + 0));
    const float4 M1  = __ldg((const float4*)(M + 4));
    const float4 M2  = __ldg((const float4*)(M + 8));
    const float4 M3  = __ldg((const float4*)(M + 12));

    // per-lane bias for the distributed sigmoid (even lane q owns state q/2)
    const float myb = (q < 2) ? bv.x : (q < 4) ? bv.y : (q < 6) ? bv.z : bv.w;

    for (int base = warp_id * 4; base < B; base += rows_per_iter) {
        const int row = base + sub;

        // ---- dot products: acc[s] = sum_d x[row][d] * W[d][s] ----
        const float4* xr = (const float4*)(x + (long)row * D_DIM);
        float acc0 = 0.f, acc1 = 0.f, acc2 = 0.f, acc3 = 0.f;
#pragma unroll
        for (int k = 0; k < 4; k++) {
            float4 xv = xr[k * 8 + q];  // elements k*32 + q*4 .. +3
            acc0 += xv.x * Wr[k][0].x + xv.y * Wr[k][1].x + xv.z * Wr[k][2].x + xv.w * Wr[k][3].x;
            acc1 += xv.x * Wr[k][0].y + xv.y * Wr[k][1].y + xv.z * Wr[k][2].y + xv.w * Wr[k][3].y;
            acc2 += xv.x * Wr[k][0].z + xv.y * Wr[k][1].z + xv.z * Wr[k][2].z + xv.w * Wr[k][3].z;
            acc3 += xv.x * Wr[k][0].w + xv.y * Wr[k][1].w + xv.z * Wr[k][2].w + xv.w * Wr[k][3].w;
        }

        // ---- 4-value reduction across 8 lanes in 4 shuffles ----
        // Round A (xor 4): merge acc0<->acc2 and acc1<->acc3 ownership.
        float sendA = (q & 4) ? acc0 : acc2;
        float keepA = (q & 4) ? acc2 : acc0;
        keepA += __shfl_xor_sync(0xffffffffu, sendA, 4);
        float sendB = (q & 4) ? acc1 : acc3;
        float keepB = (q & 4) ? acc3 : acc1;
        keepB += __shfl_xor_sync(0xffffffffu, sendB, 4);
        // Round B (xor 2): split keepA/keepB ownership.
        float send2 = (q & 2) ? keepA : keepB;
        float keep2 = (q & 2) ? keepB : keepA;
        keep2 += __shfl_xor_sync(0xffffffffu, send2, 2);
        // Round C (xor 1): finish. Even lane q now holds full acc_{q/2}.
        keep2 += __shfl_xor_sync(0xffffffffu, keep2, 1);

        // ---- distributed sigmoid (1 exp per lane; odd lanes duplicate even) ----
        float s = 1.f / (1.f + __expf(-(keep2 + myb)));

        // ---- gather s0..s3 onto lane q==0 of each group (3 shuffles) ----
        float sA = __shfl_xor_sync(0xffffffffu, s, 2);   // lane0 <- s1
        float sB = __shfl_xor_sync(0xffffffffu, s, 4);   // lane0 <- s2
        float sC = __shfl_xor_sync(0xffffffffu, sA, 4);  // lane0 <- s3

        if (q == 0) {
            float s0 = s, s1 = sA, s2 = sB, s3 = sC;

            // interfered[i] = sum_j M[i][j] * state[j]
            float i0 = M0.x * s0 + M0.y * s1 + M0.z * s2 + M0.w * s3;
            float i1 = M1.x * s0 + M1.y * s1 + M1.z * s2 + M1.w * s3;
            float i2 = M2.x * s0 + M2.y * s1 + M2.z * s2 + M2.w * s3;
            float i3 = M3.x * s0 + M3.y * s1 + M3.z * s2 + M3.w * s3;

            // bernoulli collapse decision
            float nz = __ldg(noise + row);
            float mp = 1.f / (1.f + __expf(-(nz + thr)));
            bool should_measure = __ldg(u + row) < mp;

            // gumbel-argmax (first-max tiebreak, matching jnp.argmax)
            float4 g = __ldg((const float4*)(gumbel + (long)row * 4));
            float v0 = i0 + g.x, v1 = i1 + g.y, v2 = i2 + g.z, v3 = i3 + g.w;
            float best = v0, mv = i0;
            if (v1 > best) { best = v1; mv = i1; }
            if (v2 > best) { best = v2; mv = i2; }
            if (v3 > best) { best = v3; mv = i3; }

            float mean = 0.25f * (i0 + i1 + i2 + i3);
            out[row] = should_measure ? mv : mean;
        }
    }
}

extern "C" void kernel_launch(void* const* d_in, const int* in_sizes, int n_in,
                              void* d_out, int out_size)
{
    const float* x      = (const float*)d_in[0];
    const float* W      = (const float*)d_in[1];
    const float* b      = (const float*)d_in[2];
    const float* M      = (const float*)d_in[3];
    const float* thr    = (const float*)d_in[4];
    const float* noise  = (const float*)d_in[5];
    const float* u      = (const float*)d_in[6];
    const float* gumbel = (const float*)d_in[7];
    float* out = (float*)d_out;

    int B = in_sizes[0] / D_DIM;              // 1048576
    const int threads = 256;                  // 8 warps
    const int blocks  = 2048;                 // 16384 warps -> 65536 rows/iter
    int rows_per_iter = blocks * (threads / 32) * 4;
    sn_kernel<<<blocks, threads>>>(x, W, b, M, thr, noise, u, gumbel, out,
                                   B, rows_per_iter);
}

// round 3
// speedup vs baseline: 1.9065x; 1.4277x over previous
#include <cuda_runtime.h>

// SuperpositionNeuron: out[r] = should_measure ? interfered[argmax(interfered+gumbel)]
//                                              : mean(interfered)
// interfered = sigmoid(x@W + b) @ M^T ;  B = 1048576, D = 128, S = 4.
//
// R3: 16 lanes per row (2 rows/warp) halves W register footprint -> 3 CTAs/SM.
// Epilogue inputs (noise/u/gumbel) prefetched at loop head so their DRAM
// latency overlaps the x loads + reduction chain instead of serializing.

#define D_DIM 128

__global__ void __launch_bounds__(256, 3) sn_kernel(
    const float* __restrict__ x,       // [B, 128]
    const float* __restrict__ W,       // [128, 4]
    const float* __restrict__ b,       // [4]
    const float* __restrict__ M,       // [4, 4]
    const float* __restrict__ thrp,    // [1]
    const float* __restrict__ noise,   // [B]
    const float* __restrict__ u,       // [B]
    const float* __restrict__ gumbel,  // [B, 4]
    float* __restrict__ out,           // [B]
    int B, int rows_per_iter)
{
    const int lane = threadIdx.x & 31;
    const int q    = lane & 15;  // position within row (16 lanes per row)
    const int sub  = lane >> 4;  // which of the 2 rows this warp owns

    const int warp_id = blockIdx.x * (blockDim.x >> 5) + (threadIdx.x >> 5);

    // ---- load-once constants (register-resident across the whole loop) ----
    // Lane q covers x-chunks {q, q+16}; W rows k*64 + q*4 + j.
    float4 Wr[2][4];
#pragma unroll
    for (int k = 0; k < 2; k++)
#pragma unroll
        for (int j = 0; j < 4; j++)
            Wr[k][j] = __ldg((const float4*)(W + 4 * (k * 64 + q * 4 + j)));

    const float  thr = __ldg(thrp);
    const float4 bv  = __ldg((const float4*)b);
    const float4 M0  = __ldg((const float4*)(M + 0));
    const float4 M1  = __ldg((const float4*)(M + 4));
    const float4 M2  = __ldg((const float4*)(M + 8));
    const float4 M3  = __ldg((const float4*)(M + 12));

    // state index this lane ends up owning after the reduction:
    // s_idx = bit(q,8)*2 + bit(q,4)
    const int   s_idx = (((q >> 3) & 1) << 1) | ((q >> 2) & 1);
    const float myb   = (s_idx == 0) ? bv.x : (s_idx == 1) ? bv.y
                      : (s_idx == 2) ? bv.z : bv.w;

    for (int base = warp_id * 2; base < B; base += rows_per_iter) {
        const int row = base + sub;

        // ---- prefetch epilogue inputs NOW (overlap with x-load latency) ----
        // All lanes in a group load the same address -> broadcast, ~1 sector.
        float  nz = __ldg(noise + row);
        float  uu = __ldg(u + row);
        float4 g  = __ldg((const float4*)(gumbel + (long)row * 4));

        // ---- dot products: acc[s] = sum_d x[row][d] * W[d][s] ----
        const float4* xr = (const float4*)(x + (long)row * D_DIM);
        float acc0 = 0.f, acc1 = 0.f, acc2 = 0.f, acc3 = 0.f;
#pragma unroll
        for (int k = 0; k < 2; k++) {
            float4 xv = xr[k * 16 + q];
            acc0 += xv.x * Wr[k][0].x + xv.y * Wr[k][1].x + xv.z * Wr[k][2].x + xv.w * Wr[k][3].x;
            acc1 += xv.x * Wr[k][0].y + xv.y * Wr[k][1].y + xv.z * Wr[k][2].y + xv.w * Wr[k][3].y;
            acc2 += xv.x * Wr[k][0].z + xv.y * Wr[k][1].z + xv.z * Wr[k][2].z + xv.w * Wr[k][3].z;
            acc3 += xv.x * Wr[k][0].w + xv.y * Wr[k][1].w + xv.z * Wr[k][2].w + xv.w * Wr[k][3].w;
        }

        // ---- 4-value reduction across 16 lanes in 5 shuffles ----
        // Round 1 (xor 8): split acc0/acc2 and acc1/acc3 ownership by bit 8.
        float sendA = (q & 8) ? acc0 : acc2;
        float keepA = (q & 8) ? acc2 : acc0;
        keepA += __shfl_xor_sync(0xffffffffu, sendA, 8);
        float sendB = (q & 8) ? acc1 : acc3;
        float keepB = (q & 8) ? acc3 : acc1;
        keepB += __shfl_xor_sync(0xffffffffu, sendB, 8);
        // Round 2 (xor 4): split keepA/keepB ownership by bit 4.
        float send2 = (q & 4) ? keepA : keepB;
        float keep2 = (q & 4) ? keepB : keepA;
        keep2 += __shfl_xor_sync(0xffffffffu, send2, 4);
        // Rounds 3,4: plain butterflies.
        keep2 += __shfl_xor_sync(0xffffffffu, keep2, 2);
        keep2 += __shfl_xor_sync(0xffffffffu, keep2, 1);
        // Lane q now holds full acc_{s_idx}.

        // ---- distributed sigmoid (1 exp per lane) ----
        float s = 1.f / (1.f + __expf(-(keep2 + myb)));

        // ---- gather s0..s3 onto lane q==0 of each group (3 shuffles) ----
        float sA = __shfl_xor_sync(0xffffffffu, s, 4);   // lane0 <- s1 (from q=4)
        float sB = __shfl_xor_sync(0xffffffffu, s, 8);   // lane0 <- s2 (from q=8)
        float sC = __shfl_xor_sync(0xffffffffu, sA, 8);  // lane0 <- s3 (lane8's sA, from q=12)

        if (q == 0) {
            float s0 = s, s1 = sA, s2 = sB, s3 = sC;

            // interfered[i] = sum_j M[i][j] * state[j]
            float i0 = M0.x * s0 + M0.y * s1 + M0.z * s2 + M0.w * s3;
            float i1 = M1.x * s0 + M1.y * s1 + M1.z * s2 + M1.w * s3;
            float i2 = M2.x * s0 + M2.y * s1 + M2.z * s2 + M2.w * s3;
            float i3 = M3.x * s0 + M3.y * s1 + M3.z * s2 + M3.w * s3;

            // bernoulli collapse decision
            float mp = 1.f / (1.f + __expf(-(nz + thr)));
            bool should_measure = uu < mp;

            // gumbel-argmax (first-max tiebreak, matching jnp.argmax)
            float v0 = i0 + g.x, v1 = i1 + g.y, v2 = i2 + g.z, v3 = i3 + g.w;
            float best = v0, mv = i0;
            if (v1 > best) { best = v1; mv = i1; }
            if (v2 > best) { best = v2; mv = i2; }
            if (v3 > best) { best = v3; mv = i3; }

            float mean = 0.25f * (i0 + i1 + i2 + i3);
            out[row] = should_measure ? mv : mean;
        }
    }
}

extern "C" void kernel_launch(void* const* d_in, const int* in_sizes, int n_in,
                              void* d_out, int out_size)
{
    const float* x      = (const float*)d_in[0];
    const float* W      = (const float*)d_in[1];
    const float* b      = (const float*)d_in[2];
    const float* M      = (const float*)d_in[3];
    const float* thr    = (const float*)d_in[4];
    const float* noise  = (const float*)d_in[5];
    const float* u      = (const float*)d_in[6];
    const float* gumbel = (const float*)d_in[7];
    float* out = (float*)d_out;

    int B = in_sizes[0] / D_DIM;              // 1048576
    const int threads = 256;                  // 8 warps
    const int blocks  = 456;                  // 3 CTAs/SM x 152 SMs, persistent
    int rows_per_iter = blocks * (threads / 32) * 2;
    sn_kernel<<<blocks, threads>>>(x, W, b, M, thr, noise, u, gumbel, out,
                                   B, rows_per_iter);
}

// round 4
// speedup vs baseline: 1.9250x; 1.0097x over previous
#include <cuda_runtime.h>

// SuperpositionNeuron: out[r] = should_measure ? interfered[argmax(interfered+gumbel)]
//                                              : mean(interfered)
// interfered = sigmoid(x@W + b) @ M^T ;  B = 1048576, D = 128, S = 4.
//
// R4: 1-deep software pipeline — next iteration's x tiles AND epilogue scalars
// (noise/u/gumbel) are prefetched while the current iteration's reduction /
// exp / epilogue executes, hiding the 577-cyc DRAM latency behind ~400 cyc of
// compute. M/b/threshold moved to __constant__ (uniform-register path) to pay
// for the pipeline registers and keep 3 CTAs/SM.

#define D_DIM 128

__constant__ float cM[16];
__constant__ float cb[4];
__constant__ float cthr[1];

__global__ void __launch_bounds__(256, 3) sn_kernel(
    const float* __restrict__ x,       // [B, 128]
    const float* __restrict__ W,       // [128, 4]
    const float* __restrict__ noise,   // [B]
    const float* __restrict__ u,       // [B]
    const float* __restrict__ gumbel,  // [B, 4]
    float* __restrict__ out,           // [B]
    int B, int rows_per_iter)
{
    const int lane = threadIdx.x & 31;
    const int q    = lane & 15;  // position within row (16 lanes per row)
    const int sub  = lane >> 4;  // which of the 2 rows this warp owns

    const int warp_id = blockIdx.x * (blockDim.x >> 5) + (threadIdx.x >> 5);

    // ---- W rows this lane uses, register-resident for the whole kernel ----
    float4 Wr[2][4];
#pragma unroll
    for (int k = 0; k < 2; k++)
#pragma unroll
        for (int j = 0; j < 4; j++)
            Wr[k][j] = __ldg((const float4*)(W + 4 * (k * 64 + q * 4 + j)));

    // state index this lane owns after the reduction: bit3*2 + bit2 of q
    const int   s_idx = (((q >> 3) & 1) << 1) | ((q >> 2) & 1);
    const float myb   = cb[s_idx];

    // ---- prologue: prefetch first iteration's inputs ----
    int base = warp_id * 2;                 // always < B (7296 <= 1048576)
    {
        // nothing
    }
    int row0 = base + sub;
    const float4* xr0 = (const float4*)(x + (long)row0 * D_DIM);
    float4 xa = __ldcs(xr0 + q);
    float4 xb = __ldcs(xr0 + 16 + q);
    float  nz = __ldg(noise + row0);
    float  uu = __ldg(u + row0);
    float4 g  = __ldg((const float4*)(gumbel + (long)row0 * 4));

    while (base < B) {
        const int row   = base + sub;
        const int nbase = base + rows_per_iter;
        // clamp out-of-range prefetch to a valid address (row = sub)
        const int nrow  = (nbase < B) ? (nbase + sub) : sub;

        // ---- consume current x tiles (frees xa/xb registers) ----
        float acc0, acc1, acc2, acc3;
        {
            float4 xv = xa;
            acc0 = xv.x * Wr[0][0].x + xv.y * Wr[0][1].x + xv.z * Wr[0][2].x + xv.w * Wr[0][3].x;
            acc1 = xv.x * Wr[0][0].y + xv.y * Wr[0][1].y + xv.z * Wr[0][2].y + xv.w * Wr[0][3].y;
            acc2 = xv.x * Wr[0][0].z + xv.y * Wr[0][1].z + xv.z * Wr[0][2].z + xv.w * Wr[0][3].z;
            acc3 = xv.x * Wr[0][0].w + xv.y * Wr[0][1].w + xv.z * Wr[0][2].w + xv.w * Wr[0][3].w;
            xv = xb;
            acc0 += xv.x * Wr[1][0].x + xv.y * Wr[1][1].x + xv.z * Wr[1][2].x + xv.w * Wr[1][3].x;
            acc1 += xv.x * Wr[1][0].y + xv.y * Wr[1][1].y + xv.z * Wr[1][2].y + xv.w * Wr[1][3].y;
            acc2 += xv.x * Wr[1][0].z + xv.y * Wr[1][1].z + xv.z * Wr[1][2].z + xv.w * Wr[1][3].z;
            acc3 += xv.x * Wr[1][0].w + xv.y * Wr[1][1].w + xv.z * Wr[1][2].w + xv.w * Wr[1][3].w;
        }

        // ---- prefetch NEXT iteration (overlaps reduction/exp/epilogue) ----
        const float4* xrn = (const float4*)(x + (long)nrow * D_DIM);
        float4 nxa = __ldcs(xrn + q);
        float4 nxb = __ldcs(xrn + 16 + q);
        float  nnz = __ldg(noise + nrow);
        float  nuu = __ldg(u + nrow);
        float4 ng  = __ldg((const float4*)(gumbel + (long)nrow * 4));

        // ---- 4-value reduction across 16 lanes in 5 shuffles ----
        float sendA = (q & 8) ? acc0 : acc2;
        float keepA = (q & 8) ? acc2 : acc0;
        keepA += __shfl_xor_sync(0xffffffffu, sendA, 8);
        float sendB = (q & 8) ? acc1 : acc3;
        float keepB = (q & 8) ? acc3 : acc1;
        keepB += __shfl_xor_sync(0xffffffffu, sendB, 8);
        float send2 = (q & 4) ? keepA : keepB;
        float keep2 = (q & 4) ? keepB : keepA;
        keep2 += __shfl_xor_sync(0xffffffffu, send2, 4);
        keep2 += __shfl_xor_sync(0xffffffffu, keep2, 2);
        keep2 += __shfl_xor_sync(0xffffffffu, keep2, 1);
        // lane q now holds full acc_{s_idx}

        // ---- distributed sigmoid (1 exp per lane) ----
        float s = 1.f / (1.f + __expf(-(keep2 + myb)));

        // ---- gather s0..s3 onto lane q==0 of each group (3 shuffles) ----
        float sA = __shfl_xor_sync(0xffffffffu, s, 4);
        float sB = __shfl_xor_sync(0xffffffffu, s, 8);
        float sC = __shfl_xor_sync(0xffffffffu, sA, 8);

        if (q == 0) {
            float s0 = s, s1 = sA, s2 = sB, s3 = sC;

            float i0 = cM[0]  * s0 + cM[1]  * s1 + cM[2]  * s2 + cM[3]  * s3;
            float i1 = cM[4]  * s0 + cM[5]  * s1 + cM[6]  * s2 + cM[7]  * s3;
            float i2 = cM[8]  * s0 + cM[9]  * s1 + cM[10] * s2 + cM[11] * s3;
            float i3 = cM[12] * s0 + cM[13] * s1 + cM[14] * s2 + cM[15] * s3;

            float mp = 1.f / (1.f + __expf(-(nz + cthr[0])));
            bool should_measure = uu < mp;

            // gumbel-argmax (first-max tiebreak, matching jnp.argmax)
            float v0 = i0 + g.x, v1 = i1 + g.y, v2 = i2 + g.z, v3 = i3 + g.w;
            float best = v0, mv = i0;
            if (v1 > best) { best = v1; mv = i1; }
            if (v2 > best) { best = v2; mv = i2; }
            if (v3 > best) { best = v3; mv = i3; }

            float mean = 0.25f * (i0 + i1 + i2 + i3);
            __stcs(out + row, should_measure ? mv : mean);
        }

        // ---- rotate pipeline registers ----
        base = nbase;
        xa = nxa; xb = nxb; nz = nnz; uu = nuu; g = ng;
    }
}

extern "C" void kernel_launch(void* const* d_in, const int* in_sizes, int n_in,
                              void* d_out, int out_size)
{
    const float* x      = (const float*)d_in[0];
    const float* W      = (const float*)d_in[1];
    const float* b      = (const float*)d_in[2];
    const float* M      = (const float*)d_in[3];
    const float* thr    = (const float*)d_in[4];
    const float* noise  = (const float*)d_in[5];
    const float* u      = (const float*)d_in[6];
    const float* gumbel = (const float*)d_in[7];
    float* out = (float*)d_out;

    // Small uniform params -> constant bank (D2D async copies, capturable).
    cudaMemcpyToSymbolAsync(cM,   M,   16 * sizeof(float), 0, cudaMemcpyDeviceToDevice, 0);
    cudaMemcpyToSymbolAsync(cb,   b,    4 * sizeof(float), 0, cudaMemcpyDeviceToDevice, 0);
    cudaMemcpyToSymbolAsync(cthr, thr,      sizeof(float), 0, cudaMemcpyDeviceToDevice, 0);

    int B = in_sizes[0] / D_DIM;              // 1048576
    const int threads = 256;                  // 8 warps
    const int blocks  = 456;                  // 3 CTAs/SM x 152 SMs, persistent
    int rows_per_iter = blocks * (threads / 32) * 2;   // 7296
    sn_kernel<<<blocks, threads>>>(x, W, noise, u, gumbel, out, B, rows_per_iter);
}

// round 6
// speedup vs baseline: 2.6570x; 1.3803x over previous
#include <cuda_runtime.h>

// SuperpositionNeuron: out[r] = should_measure ? interfered[argmax(interfered+gumbel)]
//                                              : mean(interfered)
// interfered = sigmoid(x@W + b) @ M^T ;  B = 1048576, D = 128, S = 4.
//
// R6: one ROW PER THREAD (R5 design, W-index bug fixed). x is transposed
// through shared memory (coalesced LDG.128 coop-load -> XOR-swizzled
// conflict-free LDS.128 per-row reads). Reading slot (cc^rx) yields element
// cc, so W is indexed by the UNSWIZZLED cc (uniform constant load).
// Double-buffered 32-column sub-tiles (2 x 32KB smem) -> 3 CTAs/SM.

#define D_DIM     128
#define TILE_ROWS 256
#define SUB_F4    8        // float4 per row per sub-tile (32 cols)

__constant__ float cW[512];   // [128][4] row-major
__constant__ float cM[16];    // [4][4]
__constant__ float cb[4];
__constant__ float cthr[1];

__global__ void __launch_bounds__(256, 3) sn_kernel(
    const float4* __restrict__ x4,      // [B, 32] float4 view of x[B,128]
    const float*  __restrict__ noise,   // [B]
    const float*  __restrict__ u,       // [B]
    const float4* __restrict__ gumbel4, // [B] float4 view of gumbel[B,4]
    float* __restrict__ out)            // [B]
{
    __shared__ float4 buf[2][TILE_ROWS * SUB_F4];   // 2 x 32 KB

    const int tid = threadIdx.x;
    const int tb  = blockIdx.x * TILE_ROWS;
    const int row = tb + tid;

    // ---- epilogue inputs: coalesced, prefetched up front ----
    float  nz = __ldg(noise + row);
    float  uu = __ldg(u + row);
    float4 g  = __ldg(gumbel4 + row);

    const int rx = tid & 7;   // XOR-swizzle key for this thread's row

    // ---- prologue: coop-load sub-tile 0 (cols 0..31) ----
    // f = i*256 + tid ; r = f>>3 ; j = f&7  -> 4 consecutive rows x 128B per warp
    float4 p[8];
#pragma unroll
    for (int i = 0; i < 8; i++) {
        int f = i * 256 + tid, r = f >> 3, j = f & 7;
        p[i] = __ldcs(x4 + (size_t)(tb + r) * 32 + j);
    }
#pragma unroll
    for (int i = 0; i < 8; i++) {
        int f = i * 256 + tid, r = f >> 3, j = f & 7;
        buf[0][r * 8 + (j ^ (r & 7))] = p[i];
    }
    __syncthreads();

    float acc0 = 0.f, acc1 = 0.f, acc2 = 0.f, acc3 = 0.f;

#pragma unroll
    for (int s = 0; s < 4; s++) {
        // prefetch next sub-tile into registers (overlaps compute below)
        if (s < 3) {
#pragma unroll
            for (int i = 0; i < 8; i++) {
                int f = i * 256 + tid, r = f >> 3, j = f & 7;
                p[i] = __ldcs(x4 + (size_t)(tb + r) * 32 + (s + 1) * 8 + j);
            }
        }

        // ---- compute: this thread's row, cols s*32 .. s*32+31 ----
        // Slot (cc^rx) holds element cc of this row; W indexed by cc
        // (compile-time uniform -> LDCU from constant bank).
#pragma unroll
        for (int cc = 0; cc < 8; cc++) {
            float4 xv = buf[s & 1][tid * 8 + (cc ^ rx)];
            const float* w = &cW[(s * 8 + cc) * 16];  // W rows 4*(s*8+cc)..+3
            acc0 += xv.x * w[0] + xv.y * w[4] + xv.z * w[8]  + xv.w * w[12];
            acc1 += xv.x * w[1] + xv.y * w[5] + xv.z * w[9]  + xv.w * w[13];
            acc2 += xv.x * w[2] + xv.y * w[6] + xv.z * w[10] + xv.w * w[14];
            acc3 += xv.x * w[3] + xv.y * w[7] + xv.z * w[11] + xv.w * w[15];
        }

        // stage next sub-tile into the other buffer
        if (s < 3) {
#pragma unroll
            for (int i = 0; i < 8; i++) {
                int f = i * 256 + tid, r = f >> 3, j = f & 7;
                buf[(s + 1) & 1][r * 8 + (j ^ (r & 7))] = p[i];
            }
            __syncthreads();
        }
    }

    // ---- dense epilogue (every lane = one row) ----
    float s0 = 1.f / (1.f + __expf(-(acc0 + cb[0])));
    float s1 = 1.f / (1.f + __expf(-(acc1 + cb[1])));
    float s2 = 1.f / (1.f + __expf(-(acc2 + cb[2])));
    float s3 = 1.f / (1.f + __expf(-(acc3 + cb[3])));

    float i0 = cM[0]  * s0 + cM[1]  * s1 + cM[2]  * s2 + cM[3]  * s3;
    float i1 = cM[4]  * s0 + cM[5]  * s1 + cM[6]  * s2 + cM[7]  * s3;
    float i2 = cM[8]  * s0 + cM[9]  * s1 + cM[10] * s2 + cM[11] * s3;
    float i3 = cM[12] * s0 + cM[13] * s1 + cM[14] * s2 + cM[15] * s3;

    float mp = 1.f / (1.f + __expf(-(nz + cthr[0])));
    bool should_measure = uu < mp;

    // gumbel-argmax (first-max tiebreak, matching jnp.argmax)
    float v0 = i0 + g.x, v1 = i1 + g.y, v2 = i2 + g.z, v3 = i3 + g.w;
    float best = v0, mv = i0;
    if (v1 > best) { best = v1; mv = i1; }
    if (v2 > best) { best = v2; mv = i2; }
    if (v3 > best) { best = v3; mv = i3; }

    float mean = 0.25f * (i0 + i1 + i2 + i3);
    __stcs(out + row, should_measure ? mv : mean);
}

extern "C" void kernel_launch(void* const* d_in, const int* in_sizes, int n_in,
                              void* d_out, int out_size)
{
    const float* x      = (const float*)d_in[0];
    const float* W      = (const float*)d_in[1];
    const float* b      = (const float*)d_in[2];
    const float* M      = (const float*)d_in[3];
    const float* thr    = (const float*)d_in[4];
    const float* noise  = (const float*)d_in[5];
    const float* u      = (const float*)d_in[6];
    const float* gumbel = (const float*)d_in[7];
    float* out = (float*)d_out;

    // small uniform params -> constant bank (D2D async copies, capturable)
    cudaMemcpyToSymbolAsync(cW,   W,   512 * sizeof(float), 0, cudaMemcpyDeviceToDevice, 0);
    cudaMemcpyToSymbolAsync(cM,   M,    16 * sizeof(float), 0, cudaMemcpyDeviceToDevice, 0);
    cudaMemcpyToSymbolAsync(cb,   b,     4 * sizeof(float), 0, cudaMemcpyDeviceToDevice, 0);
    cudaMemcpyToSymbolAsync(cthr, thr,       sizeof(float), 0, cudaMemcpyDeviceToDevice, 0);

    int B = in_sizes[0] / D_DIM;              // 1048576
    int blocks = B / TILE_ROWS;               // 4096
    sn_kernel<<<blocks, TILE_ROWS>>>((const float4*)x, noise, u,
                                     (const float4*)gumbel, out);
}